// round 6
// baseline (speedup 1.0000x reference)
#include <cuda_runtime.h>
#include <cuda_bf16.h>

// Problem constants
#define Bsz   128
#define Tlen  80
#define Edim  100
#define Udim  512

// Launch shape: 4 independent row-groups x 32 col-slice CTAs
#define NCTA  128
#define NTHR  128
#define GSZ   32
#define NGRP  4
#define RPC   32
#define PADK  516

#define APAD  40            // phase-A reduction pad
#define BPAD  20            // phase-B reduction pad

// SMEM layout (float offsets)
#define OFF_WA 0                          // 32 cols x PADK
#define OFF_WB (32 * PADK)                // 16 cols x PADK
#define OFF_H  (OFF_WB + 16 * PADK)       // 32 rows x PADK
#define OFF_RED (OFF_H + RPC * PADK)
#define SMEM_FLOATS (OFF_RED + 4 * 32 * APAD)
#define SMEM_BYTES  (SMEM_FLOATS * 4)     // 185600 B

typedef unsigned long long u64;

// Device-global scratch
__device__ float g_P0[Tlen * Bsz * Udim];
__device__ float g_h [Bsz * Udim];
__device__ float g_h0[Bsz * Udim];
__device__ float g_r1[Bsz * Udim];
__device__ unsigned g_fa[NGRP][GSZ];   // phase-A completion flags (value = steps done)
__device__ unsigned g_fb[NGRP][GSZ];   // phase-B completion flags

// ---------------- helpers ----------------

__device__ __forceinline__ u64 ffma2(u64 a, u64 b, u64 c) {
    u64 d;
    asm("fma.rn.f32x2 %0, %1, %2, %3;" : "=l"(d) : "l"(a), "l"(b), "l"(c));
    return d;
}

__device__ __forceinline__ float fsum(u64 v) {
    float lo, hi;
    asm("mov.b64 {%0, %1}, %2;" : "=f"(lo), "=f"(hi) : "l"(v));
    return lo + hi;
}

__device__ __forceinline__ float tanh_fast(float x) {
    float e = __expf(2.0f * x);
    return 1.0f - __fdividef(2.0f, e + 1.0f);
}

__device__ __forceinline__ void st_rel(unsigned* p, unsigned v) {
    asm volatile("st.release.gpu.global.u32 [%0], %1;" :: "l"(p), "r"(v) : "memory");
}
__device__ __forceinline__ unsigned ld_acq(const unsigned* p) {
    unsigned v;
    asm volatile("ld.acquire.gpu.global.u32 %0, [%1];" : "=r"(v) : "l"(p) : "memory");
    return v;
}

// Warp-collective: wait until all 32 flags (one 128B line) reach target.
// Each lane polls one flag; one coalesced wavefront per poll iteration.
__device__ __forceinline__ void wait_flags(const unsigned* f, unsigned target) {
    const int lane = threadIdx.x & 31;
    unsigned v;
    do { v = ld_acq(f + lane); }
    while (!__all_sync(0xffffffffu, v >= target));
}

// ---------------- kernel 1: P0 = emb[tokens] @ k0 + b0 ----------------

#define PC_PAIRS 16

__global__ void __launch_bounds__(NTHR) pre_kernel(
    const int* __restrict__ tokens, const float* __restrict__ emb,
    const float* __restrict__ k0, const float* __restrict__ b0)
{
    __shared__ int    tok[PC_PAIRS];
    __shared__ float2 xs2[PC_PAIRS][Edim];

    const int tid = threadIdx.x;

    if (blockIdx.x == 0 && tid < NGRP * GSZ) {
        ((unsigned*)g_fa)[tid] = 0u;
        ((unsigned*)g_fb)[tid] = 0u;
    }

    if (blockIdx.x < 64) {
        int base = blockIdx.x * 1024 + tid * 8;
        float4 z = make_float4(0.f, 0.f, 0.f, 0.f);
        *(float4*)(g_h + base)     = z;
        *(float4*)(g_h + base + 4) = z;
    }

    const int pbase = blockIdx.x * PC_PAIRS;
    if (tid < PC_PAIRS) tok[tid] = tokens[pbase + tid];
    __syncthreads();

    for (int e = tid; e < PC_PAIRS * Edim; e += NTHR) {
        int p = e / Edim, k = e - p * Edim;
        float v = emb[tok[p] * Edim + k];
        xs2[p][k] = make_float2(v, v);
    }
    __syncthreads();

    const int u = tid * 4;
    u64 acc[PC_PAIRS][2];
#pragma unroll
    for (int p = 0; p < PC_PAIRS; p++) { acc[p][0] = 0ull; acc[p][1] = 0ull; }

    for (int k = 0; k < Edim; k++) {
        ulonglong2 wv = *(const ulonglong2*)(k0 + k * Udim + u);
#pragma unroll
        for (int p = 0; p < PC_PAIRS; p++) {
            u64 x2 = *(const u64*)&xs2[p][k];
            acc[p][0] = ffma2(x2, wv.x, acc[p][0]);
            acc[p][1] = ffma2(x2, wv.y, acc[p][1]);
        }
    }

    float4 bv = *(const float4*)(b0 + u);
#pragma unroll
    for (int p = 0; p < PC_PAIRS; p++) {
        int pi = pbase + p;
        int b = pi / Tlen;
        int t = pi - b * Tlen;
        float2 lo, hi;
        asm("mov.b64 {%0, %1}, %2;" : "=f"(lo.x), "=f"(lo.y) : "l"(acc[p][0]));
        asm("mov.b64 {%0, %1}, %2;" : "=f"(hi.x), "=f"(hi.y) : "l"(acc[p][1]));
        float4 o = make_float4(lo.x + bv.x, lo.y + bv.y, hi.x + bv.z, hi.y + bv.w);
        *(float4*)(g_P0 + ((size_t)(t * Bsz) + b) * Udim + u) = o;
    }
}

// ---------------- kernel 2: persistent scan ----------------
// CTA (g, j): g = row group (32 rows), j = col slice. K split across 4 warps.
// Synchronization: per-CTA monotonic step flags (fa = phase-A done, fb =
// phase-B done). Each warp polls the full 32-flag line before its FMA:
//   A(t) FMA needs all fb >= t   (h(t) written AND h0(t-1) readers done)
//   B(t) FMA needs all fa >= t+1 (h0/r1(t) written AND h(t) readers done)
// Warp w loads its own H K-slice [:, 128w..128w+128) software-pipelined.

__global__ void __launch_bounds__(NTHR, 1) rnn_kernel(
    const float* __restrict__ rk0, const float* __restrict__ rk1,
    const float* __restrict__ k1,  const float* __restrict__ b1,
    const float* __restrict__ wd,  const float* __restrict__ bd,
    float* __restrict__ out)
{
    extern __shared__ float sm[];
    const int tid  = threadIdx.x;
    const int g    = blockIdx.x >> 5;
    const int j    = blockIdx.x & 31;
    const int r0   = g * RPC;
    const int w    = tid >> 5;
    const int lane = tid & 31;
    const bool isA0 = (j < 16);

    // --- load weight slices into SMEM (once), transposed [col][K] ---
    const float* wsrcA = isA0 ? rk0 : rk1;
    const int cbaseA = (j & 15) * 32;
    for (int e = tid; e < 32 * Udim; e += NTHR) {
        int k = e >> 5, cc = e & 31;
        sm[OFF_WA + cc * PADK + k] = wsrcA[k * Udim + cbaseA + cc];
    }
    const int cbaseB = j * 16;
    for (int e = tid; e < 16 * Udim; e += NTHR) {
        int k = e >> 4, cc = e & 15;
        sm[OFF_WB + cc * PADK + k] = k1[k * Udim + cbaseB + cc];
    }

    // phase-A lane geometry: rows rg+4i (i<8), cols cg+8jj (jj<4)
    const int rg = lane & 3;
    const int cg = lane >> 2;
    // phase-B lane geometry: rows rgB+8i (i<4), cols cgB+4jj (jj<4)
    const int rgB = lane & 7;
    const int cgB = lane >> 3;

    float b1v[4];
#pragma unroll
    for (int jj = 0; jj < 4; jj++)
        b1v[jj] = isA0 ? 0.f : b1[cbaseA + cg + 8 * jj];
    __syncthreads();

    const float* HpA = sm + OFF_H  + w * 128;
    float*       HTw = sm + OFF_H  + w * 128;
    const float* WpA = sm + OFF_WA + w * 128;
    const float* WpB = sm + OFF_WB + w * 128;
    float* redw  = sm + OFF_RED + w * 32 * APAD;
    float* redwB = sm + OFF_RED + w * 32 * BPAD;

    const int lrow[8] = { lane >> 3, 4 + (lane >> 3), 8 + (lane >> 3), 12 + (lane >> 3),
                          16 + (lane >> 3), 20 + (lane >> 3), 24 + (lane >> 3), 28 + (lane >> 3) };
    const int lkq = lane & 7;

    unsigned* fa = g_fa[g];
    unsigned* fb = g_fb[g];

    for (int t = 0; t < Tlen; t++) {
        // ================= Phase A: h @ [rk0 | rk1] =================
        // P0 prefetch (static data, safe before the flag wait)
        float pv[2][4];
        if (isA0) {
#pragma unroll
            for (int ii = 0; ii < 2; ii++) {
                int lr = rg + 4 * (2 * w + ii);
                const float* p0 = g_P0 + ((size_t)t * Bsz + r0 + lr) * Udim + cbaseA;
#pragma unroll
                for (int jj = 0; jj < 4; jj++)
                    pv[ii][jj] = __ldcg(p0 + cg + 8 * jj);
            }
        }

        wait_flags(fb, (unsigned)t);     // h(t) ready; h0(t-1) readers done

        u64 acc[8][4];
#pragma unroll
        for (int i = 0; i < 8; i++)
#pragma unroll
            for (int jj = 0; jj < 4; jj++) acc[i][jj] = 0ull;

        {
            const float* gA = g_h + (size_t)r0 * Udim + w * 128;
            float4 buf[8];
#pragma unroll
            for (int i = 0; i < 8; i++)
                buf[i] = __ldcg((const float4*)(gA + lrow[i] * Udim) + lkq);

#pragma unroll
            for (int b = 0; b < 4; b++) {
#pragma unroll
                for (int i = 0; i < 8; i++)
                    *(float4*)(HTw + lrow[i] * PADK + b * 32 + lkq * 4) = buf[i];
                if (b < 3) {
#pragma unroll
                    for (int i = 0; i < 8; i++)
                        buf[i] = __ldcg((const float4*)(gA + lrow[i] * Udim + (b + 1) * 32) + lkq);
                }
                __syncwarp();
#pragma unroll
                for (int kc = 0; kc < 8; kc++) {
                    const int k = b * 32 + kc * 4;
                    ulonglong2 Wv[4];
#pragma unroll
                    for (int jj = 0; jj < 4; jj++)
                        Wv[jj] = *(const ulonglong2*)(WpA + (cg + 8 * jj) * PADK + k);
#pragma unroll
                    for (int i = 0; i < 8; i++) {
                        ulonglong2 Hv = *(const ulonglong2*)(HpA + (rg + 4 * i) * PADK + k);
#pragma unroll
                        for (int jj = 0; jj < 4; jj++) {
                            acc[i][jj] = ffma2(Hv.x, Wv[jj].x, acc[i][jj]);
                            acc[i][jj] = ffma2(Hv.y, Wv[jj].y, acc[i][jj]);
                        }
                    }
                }
            }
        }

        // store partials (bank = 8*rg + cg + const; conflict-free)
#pragma unroll
        for (int i = 0; i < 8; i++)
#pragma unroll
            for (int jj = 0; jj < 4; jj++)
                redw[(rg + 4 * i) * APAD + cg + 8 * jj] = fsum(acc[i][jj]);
        __syncthreads();

        // finalize rows 2w, 2w+1 tiles
#pragma unroll
        for (int ii = 0; ii < 2; ii++) {
            int lr = rg + 4 * (2 * w + ii);
            int grow = (r0 + lr) * Udim + cbaseA;
#pragma unroll
            for (int jj = 0; jj < 4; jj++) {
                int lcol = cg + 8 * jj;
                float s = sm[OFF_RED + 0 * 32 * APAD + lr * APAD + lcol]
                        + sm[OFF_RED + 1 * 32 * APAD + lr * APAD + lcol]
                        + sm[OFF_RED + 2 * 32 * APAD + lr * APAD + lcol]
                        + sm[OFF_RED + 3 * 32 * APAD + lr * APAD + lcol];
                if (isA0) g_h0[grow + lcol] = tanh_fast(s + pv[ii][jj]);
                else      g_r1[grow + lcol] = s + b1v[jj];
            }
        }
        __syncthreads();
        if (tid == 0) st_rel(&fa[j], (unsigned)(t + 1));

        // ================= Phase B: h0 @ k1 =================
        wait_flags(fa, (unsigned)(t + 1));   // h0/r1(t) ready; h(t) readers done

        float r1v[4];
        {
            const float* r1p = g_r1 + (size_t)(r0 + rgB + 8 * w) * Udim + cbaseB;
#pragma unroll
            for (int jj = 0; jj < 4; jj++)
                r1v[jj] = __ldcg(r1p + cgB + 4 * jj);
        }

        u64 acc2[4][4];
#pragma unroll
        for (int i = 0; i < 4; i++)
#pragma unroll
            for (int jj = 0; jj < 4; jj++) acc2[i][jj] = 0ull;

        {
            const float* gB = g_h0 + (size_t)r0 * Udim + w * 128;
            float4 buf[8];
#pragma unroll
            for (int i = 0; i < 8; i++)
                buf[i] = __ldcg((const float4*)(gB + lrow[i] * Udim) + lkq);

#pragma unroll
            for (int b = 0; b < 4; b++) {
#pragma unroll
                for (int i = 0; i < 8; i++)
                    *(float4*)(HTw + lrow[i] * PADK + b * 32 + lkq * 4) = buf[i];
                if (b < 3) {
#pragma unroll
                    for (int i = 0; i < 8; i++)
                        buf[i] = __ldcg((const float4*)(gB + lrow[i] * Udim + (b + 1) * 32) + lkq);
                }
                __syncwarp();
#pragma unroll
                for (int kc = 0; kc < 8; kc++) {
                    const int k = b * 32 + kc * 4;
                    ulonglong2 Wv[4];
#pragma unroll
                    for (int jj = 0; jj < 4; jj++)
                        Wv[jj] = *(const ulonglong2*)(WpB + (cgB + 4 * jj) * PADK + k);
#pragma unroll
                    for (int i = 0; i < 4; i++) {
                        ulonglong2 Hv = *(const ulonglong2*)(HpA + (rgB + 8 * i) * PADK + k);
#pragma unroll
                        for (int jj = 0; jj < 4; jj++) {
                            acc2[i][jj] = ffma2(Hv.x, Wv[jj].x, acc2[i][jj]);
                            acc2[i][jj] = ffma2(Hv.y, Wv[jj].y, acc2[i][jj]);
                        }
                    }
                }
            }
        }

        // store partials (bank = 20*rgB + cgB + const; distinct)
#pragma unroll
        for (int i = 0; i < 4; i++)
#pragma unroll
            for (int jj = 0; jj < 4; jj++)
                redwB[(rgB + 8 * i) * BPAD + cgB + 4 * jj] = fsum(acc2[i][jj]);
        __syncthreads();

        {
            int lr = rgB + 8 * w;
            int grow = (r0 + lr) * Udim + cbaseB;
#pragma unroll
            for (int jj = 0; jj < 4; jj++) {
                int lcol = cgB + 4 * jj;
                float s = sm[OFF_RED + 0 * 32 * BPAD + lr * BPAD + lcol]
                        + sm[OFF_RED + 1 * 32 * BPAD + lr * BPAD + lcol]
                        + sm[OFF_RED + 2 * 32 * BPAD + lr * BPAD + lcol]
                        + sm[OFF_RED + 3 * 32 * BPAD + lr * BPAD + lcol];
                g_h[grow + lcol] = tanh_fast(s + r1v[jj]);
            }
        }
        __syncthreads();
        if (tid == 0) st_rel(&fb[j], (unsigned)(t + 1));
    }

    // ---- output head: sigmoid(h @ wd + bd), CTA j==0 of each group ----
    if (j == 0) {
        wait_flags(fb, (unsigned)Tlen);     // whole group's final h written
        int row = r0 + (tid >> 2);
        int p   = tid & 3;
        const float4* hv = (const float4*)(g_h + row * Udim + p * 128);
        const float4* wv = (const float4*)(wd + p * 128);
        float s = 0.f;
#pragma unroll 8
        for (int q = 0; q < 32; q++) {
            float4 a = __ldcg(hv + q);
            float4 b = wv[q];
            s += a.x * b.x + a.y * b.y + a.z * b.z + a.w * b.w;
        }
        s += __shfl_xor_sync(0xffffffffu, s, 1);
        s += __shfl_xor_sync(0xffffffffu, s, 2);
        if (p == 0) out[row] = 1.0f / (1.0f + __expf(-(s + bd[0])));
    }
}

// ---------------- launch ----------------

extern "C" void kernel_launch(void* const* d_in, const int* in_sizes, int n_in,
                              void* d_out, int out_size) {
    const int*   tokens = (const int*)  d_in[0];
    const float* emb    = (const float*)d_in[1];
    const float* k0     = (const float*)d_in[2];
    const float* rk0    = (const float*)d_in[3];
    const float* b0     = (const float*)d_in[4];
    const float* k1     = (const float*)d_in[5];
    const float* rk1    = (const float*)d_in[6];
    const float* b1     = (const float*)d_in[7];
    const float* wd     = (const float*)d_in[8];
    const float* bd     = (const float*)d_in[9];
    float* out = (float*)d_out;

    (void)in_sizes; (void)n_in; (void)out_size;

    cudaFuncSetAttribute(rnn_kernel, cudaFuncAttributeMaxDynamicSharedMemorySize, SMEM_BYTES);

    pre_kernel<<<(Bsz * Tlen) / PC_PAIRS, NTHR>>>(tokens, emb, k0, b0);
    rnn_kernel<<<NCTA, NTHR, SMEM_BYTES>>>(rk0, rk1, k1, b1, wd, bd, out);
}

// round 7
// speedup vs baseline: 2.2225x; 2.2225x over previous
#include <cuda_runtime.h>
#include <cuda_bf16.h>

// Problem constants
#define Bsz   128
#define Tlen  80
#define Edim  100
#define Udim  512

// Launch shape: 4 independent row-groups x 32 col-slice CTAs, 8 warps/CTA
#define NCTA  128
#define NTHR  256
#define NWARP 8
#define GSZ   32
#define NGRP  4
#define RPC   32
#define PADK  516

#define APAD  40            // phase-A reduction pad (8*rg+cg banks distinct)
#define BPAD  20            // phase-B reduction pad (20*rgB+cgB banks distinct)

// SMEM layout (float offsets)
#define OFF_WA 0                          // 32 cols x PADK
#define OFF_WB (32 * PADK)                // 16 cols x PADK
#define OFF_H  (OFF_WB + 16 * PADK)       // 32 rows x PADK
#define OFF_RED (OFF_H + RPC * PADK)      // 8 warps x 32 x APAD
#define SMEM_FLOATS (OFF_RED + NWARP * 32 * APAD)
#define SMEM_BYTES  (SMEM_FLOATS * 4)     // 206080 B <= 232448

typedef unsigned long long u64;

// Device-global scratch
__device__ float g_P0[Tlen * Bsz * Udim];
__device__ float g_h [Bsz * Udim];
__device__ float g_h0[Bsz * Udim];
__device__ float g_r1[Bsz * Udim];
__device__ unsigned g_ctr[NGRP * 128];      // one counter per group, 512B apart

// ---------------- helpers ----------------

__device__ __forceinline__ u64 ffma2(u64 a, u64 b, u64 c) {
    u64 d;
    asm("fma.rn.f32x2 %0, %1, %2, %3;" : "=l"(d) : "l"(a), "l"(b), "l"(c));
    return d;
}

__device__ __forceinline__ float fsum(u64 v) {
    float lo, hi;
    asm("mov.b64 {%0, %1}, %2;" : "=f"(lo), "=f"(hi) : "l"(v));
    return lo + hi;
}

__device__ __forceinline__ float tanh_fast(float x) {
    float e = __expf(2.0f * x);
    return 1.0f - __fdividef(2.0f, e + 1.0f);
}

// Group barrier (R4-proven): monotonic counter, release-red arrive +
// acquire-load poll by one thread.
__device__ __forceinline__ void gbar(unsigned* ctr, unsigned target) {
    __syncthreads();
    if (threadIdx.x == 0) {
        asm volatile("red.release.gpu.global.add.u32 [%0], %1;"
                     :: "l"(ctr), "r"(1u) : "memory");
        unsigned v;
        do {
            asm volatile("ld.acquire.gpu.global.u32 %0, [%1];"
                         : "=r"(v) : "l"(ctr) : "memory");
        } while (v < target);
    }
    __syncthreads();
}

// Load 32 rows x 512 cols into padded SMEM tile (L2-only loads). 256 threads.
__device__ __forceinline__ void load_ht(float* HT, const float* src) {
    const float4* s = (const float4*)src;
#pragma unroll
    for (int i = 0; i < 16; i++) {
        int e = threadIdx.x + i * NTHR;      // 0..4095
        int r = e >> 7, kq = e & 127;
        float4 v = __ldcg(s + e);
        *(float4*)(HT + r * PADK + (kq << 2)) = v;
    }
}

// ---------------- kernel 1: P0 = emb[tokens] @ k0 + b0 ----------------

#define PC_PAIRS 16
#define PTHR 128

__global__ void __launch_bounds__(PTHR) pre_kernel(
    const int* __restrict__ tokens, const float* __restrict__ emb,
    const float* __restrict__ k0, const float* __restrict__ b0)
{
    __shared__ int    tok[PC_PAIRS];
    __shared__ float2 xs2[PC_PAIRS][Edim];

    const int tid = threadIdx.x;

    if (blockIdx.x == 0 && tid < NGRP) g_ctr[tid * 128] = 0;

    if (blockIdx.x < 64) {
        int base = blockIdx.x * 1024 + tid * 8;
        float4 z = make_float4(0.f, 0.f, 0.f, 0.f);
        *(float4*)(g_h + base)     = z;
        *(float4*)(g_h + base + 4) = z;
    }

    const int pbase = blockIdx.x * PC_PAIRS;
    if (tid < PC_PAIRS) tok[tid] = tokens[pbase + tid];
    __syncthreads();

    for (int e = tid; e < PC_PAIRS * Edim; e += PTHR) {
        int p = e / Edim, k = e - p * Edim;
        float v = emb[tok[p] * Edim + k];
        xs2[p][k] = make_float2(v, v);
    }
    __syncthreads();

    const int u = tid * 4;
    u64 acc[PC_PAIRS][2];
#pragma unroll
    for (int p = 0; p < PC_PAIRS; p++) { acc[p][0] = 0ull; acc[p][1] = 0ull; }

    for (int k = 0; k < Edim; k++) {
        ulonglong2 wv = *(const ulonglong2*)(k0 + k * Udim + u);
#pragma unroll
        for (int p = 0; p < PC_PAIRS; p++) {
            u64 x2 = *(const u64*)&xs2[p][k];
            acc[p][0] = ffma2(x2, wv.x, acc[p][0]);
            acc[p][1] = ffma2(x2, wv.y, acc[p][1]);
        }
    }

    float4 bv = *(const float4*)(b0 + u);
#pragma unroll
    for (int p = 0; p < PC_PAIRS; p++) {
        int pi = pbase + p;
        int b = pi / Tlen;
        int t = pi - b * Tlen;
        float2 lo, hi;
        asm("mov.b64 {%0, %1}, %2;" : "=f"(lo.x), "=f"(lo.y) : "l"(acc[p][0]));
        asm("mov.b64 {%0, %1}, %2;" : "=f"(hi.x), "=f"(hi.y) : "l"(acc[p][1]));
        float4 o = make_float4(lo.x + bv.x, lo.y + bv.y, hi.x + bv.z, hi.y + bv.w);
        *(float4*)(g_P0 + ((size_t)(t * Bsz) + b) * Udim + u) = o;
    }
}

// ---------------- kernel 2: persistent scan ----------------
// CTA (g, j): g = row group (32 rows), j = col slice. 8 warps; warp w owns
// K-slice [64w, 64w+64). Partials reduced through SMEM (8 buffers).
// Phase A: j<16 -> rk0 cols j*32..+31 (-> h0); j>=16 -> rk1 cols (-> r1).
//   warp tile: rows rg+4i (rg=lane&3, i<8), cols cg+8jj (cg=lane>>2, jj<4)
// Phase B: k1 cols j*16..+15 (-> next h).
//   warp tile: rows rgB+8i (rgB=lane&7, i<4), cols cgB+4jj (cgB=lane>>3, jj<4)
// Finalize (256 threads): A row=tid>>3, 4 cols (tid&7)*4; B row=tid>>3, 2 cols.

__global__ void __launch_bounds__(NTHR, 1) rnn_kernel(
    const float* __restrict__ rk0, const float* __restrict__ rk1,
    const float* __restrict__ k1,  const float* __restrict__ b1,
    const float* __restrict__ wd,  const float* __restrict__ bd,
    float* __restrict__ out)
{
    extern __shared__ float sm[];
    const int tid  = threadIdx.x;
    const int g    = blockIdx.x >> 5;
    const int j    = blockIdx.x & 31;
    const int r0   = g * RPC;
    const int w    = tid >> 5;
    const int lane = tid & 31;
    const bool isA0 = (j < 16);

    unsigned* ctr = g_ctr + g * 128;
    unsigned nbar = 0;

    // --- load weight slices into SMEM (once), transposed [col][K] ---
    const float* wsrcA = isA0 ? rk0 : rk1;
    const int cbaseA = (j & 15) * 32;
    for (int e = tid; e < 32 * Udim; e += NTHR) {
        int k = e >> 5, cc = e & 31;
        sm[OFF_WA + cc * PADK + k] = wsrcA[k * Udim + cbaseA + cc];
    }
    const int cbaseB = j * 16;
    for (int e = tid; e < 16 * Udim; e += NTHR) {
        int k = e >> 4, cc = e & 15;
        sm[OFF_WB + cc * PADK + k] = k1[k * Udim + cbaseB + cc];
    }

    // warp FMA geometry
    const int rg  = lane & 3;
    const int cg  = lane >> 2;
    const int rgB = lane & 7;
    const int cgB = lane >> 3;

    // finalize geometry (across all 256 threads)
    const int frow = tid >> 3;            // 0..31
    const int fcA  = (tid & 7) * 4;       // phase-A 4 cols
    const int fcB  = (tid & 7) * 2;       // phase-B 2 cols

    float4 b1v = make_float4(0.f, 0.f, 0.f, 0.f);
    if (!isA0) b1v = *(const float4*)(b1 + cbaseA + fcA);
    __syncthreads();

    const float* HpA = sm + OFF_H  + w * 64;   // warp's K-slice base
    const float* WpA = sm + OFF_WA + w * 64;
    const float* WpB = sm + OFF_WB + w * 64;
    float* redw  = sm + OFF_RED + w * 32 * APAD;
    float* redwB = sm + OFF_RED + w * 32 * BPAD;

    for (int t = 0; t < Tlen; t++) {
        // ================= Phase A: h @ [rk0 | rk1] =================
        float4 pv = make_float4(0.f, 0.f, 0.f, 0.f);
        if (isA0)
            pv = __ldcg((const float4*)(g_P0 + ((size_t)t * Bsz + r0 + frow) * Udim
                                        + cbaseA + fcA));

        load_ht(sm + OFF_H, g_h + r0 * Udim);
        __syncthreads();

        u64 acc[8][4];
#pragma unroll
        for (int i = 0; i < 8; i++)
#pragma unroll
            for (int jj = 0; jj < 4; jj++) acc[i][jj] = 0ull;

#pragma unroll 2
        for (int kc = 0; kc < 16; kc++) {
            const int k = kc * 4;
            ulonglong2 Wv[4];
#pragma unroll
            for (int jj = 0; jj < 4; jj++)
                Wv[jj] = *(const ulonglong2*)(WpA + (cg + 8 * jj) * PADK + k);
#pragma unroll
            for (int i = 0; i < 8; i++) {
                ulonglong2 Hv = *(const ulonglong2*)(HpA + (rg + 4 * i) * PADK + k);
#pragma unroll
                for (int jj = 0; jj < 4; jj++) {
                    acc[i][jj] = ffma2(Hv.x, Wv[jj].x, acc[i][jj]);
                    acc[i][jj] = ffma2(Hv.y, Wv[jj].y, acc[i][jj]);
                }
            }
        }

        // store partials (bank = 8*rg + cg + const; conflict-free)
#pragma unroll
        for (int i = 0; i < 8; i++)
#pragma unroll
            for (int jj = 0; jj < 4; jj++)
                redw[(rg + 4 * i) * APAD + cg + 8 * jj] = fsum(acc[i][jj]);
        __syncthreads();

        // finalize: 4 outputs/thread, float4 over 8 partials
        {
            float4 s = make_float4(0.f, 0.f, 0.f, 0.f);
#pragma unroll
            for (int p = 0; p < NWARP; p++) {
                float4 v = *(const float4*)(sm + OFF_RED + p * 32 * APAD
                                            + frow * APAD + fcA);
                s.x += v.x; s.y += v.y; s.z += v.z; s.w += v.w;
            }
            int grow = (r0 + frow) * Udim + cbaseA + fcA;
            if (isA0) {
                float4 o;
                o.x = tanh_fast(s.x + pv.x);
                o.y = tanh_fast(s.y + pv.y);
                o.z = tanh_fast(s.z + pv.z);
                o.w = tanh_fast(s.w + pv.w);
                *(float4*)(g_h0 + grow) = o;
            } else {
                float4 o = make_float4(s.x + b1v.x, s.y + b1v.y,
                                       s.z + b1v.z, s.w + b1v.w);
                *(float4*)(g_r1 + grow) = o;
            }
        }
        nbar++; gbar(ctr, nbar * GSZ);

        // ================= Phase B: h0 @ k1 =================
        float2 r1v = __ldcg((const float2*)(g_r1 + (size_t)(r0 + frow) * Udim
                                            + cbaseB + fcB));

        load_ht(sm + OFF_H, g_h0 + r0 * Udim);
        __syncthreads();

        u64 acc2[4][4];
#pragma unroll
        for (int i = 0; i < 4; i++)
#pragma unroll
            for (int jj = 0; jj < 4; jj++) acc2[i][jj] = 0ull;

#pragma unroll 2
        for (int kc = 0; kc < 16; kc++) {
            const int k = kc * 4;
            ulonglong2 Wv[4];
#pragma unroll
            for (int jj = 0; jj < 4; jj++)
                Wv[jj] = *(const ulonglong2*)(WpB + (cgB + 4 * jj) * PADK + k);
#pragma unroll
            for (int i = 0; i < 4; i++) {
                ulonglong2 Hv = *(const ulonglong2*)(HpA + (rgB + 8 * i) * PADK + k);
#pragma unroll
                for (int jj = 0; jj < 4; jj++) {
                    acc2[i][jj] = ffma2(Hv.x, Wv[jj].x, acc2[i][jj]);
                    acc2[i][jj] = ffma2(Hv.y, Wv[jj].y, acc2[i][jj]);
                }
            }
        }

        // store partials (bank = 20*rgB + cgB + const; conflict-free)
#pragma unroll
        for (int i = 0; i < 4; i++)
#pragma unroll
            for (int jj = 0; jj < 4; jj++)
                redwB[(rgB + 8 * i) * BPAD + cgB + 4 * jj] = fsum(acc2[i][jj]);
        __syncthreads();

        // finalize: 2 outputs/thread, float2 over 8 partials
        {
            float2 s = make_float2(0.f, 0.f);
#pragma unroll
            for (int p = 0; p < NWARP; p++) {
                float2 v = *(const float2*)(sm + OFF_RED + p * 32 * BPAD
                                            + frow * BPAD + fcB);
                s.x += v.x; s.y += v.y;
            }
            int grow = (r0 + frow) * Udim + cbaseB + fcB;
            float2 o;
            o.x = tanh_fast(s.x + r1v.x);
            o.y = tanh_fast(s.y + r1v.y);
            *(float2*)(g_h + grow) = o;
        }
        nbar++; gbar(ctr, nbar * GSZ);
    }

    // ---- output head: sigmoid(h @ wd + bd), CTA j==0 of each group ----
    if (j == 0) {
        int row = r0 + (tid >> 3);          // 32 rows, 8 threads each
        int p   = tid & 7;
        const float4* hv = (const float4*)(g_h + row * Udim + p * 64);
        const float4* wv = (const float4*)(wd + p * 64);
        float s = 0.f;
#pragma unroll
        for (int q = 0; q < 16; q++) {
            float4 a = __ldcg(hv + q);
            float4 b = wv[q];
            s += a.x * b.x + a.y * b.y + a.z * b.z + a.w * b.w;
        }
        s += __shfl_xor_sync(0xffffffffu, s, 1);
        s += __shfl_xor_sync(0xffffffffu, s, 2);
        s += __shfl_xor_sync(0xffffffffu, s, 4);
        if (p == 0) out[row] = 1.0f / (1.0f + __expf(-(s + bd[0])));
    }
}

// ---------------- launch ----------------

extern "C" void kernel_launch(void* const* d_in, const int* in_sizes, int n_in,
                              void* d_out, int out_size) {
    const int*   tokens = (const int*)  d_in[0];
    const float* emb    = (const float*)d_in[1];
    const float* k0     = (const float*)d_in[2];
    const float* rk0    = (const float*)d_in[3];
    const float* b0     = (const float*)d_in[4];
    const float* k1     = (const float*)d_in[5];
    const float* rk1    = (const float*)d_in[6];
    const float* b1     = (const float*)d_in[7];
    const float* wd     = (const float*)d_in[8];
    const float* bd     = (const float*)d_in[9];
    float* out = (float*)d_out;

    (void)in_sizes; (void)n_in; (void)out_size;

    cudaFuncSetAttribute(rnn_kernel, cudaFuncAttributeMaxDynamicSharedMemorySize, SMEM_BYTES);

    pre_kernel<<<(Bsz * Tlen) / PC_PAIRS, PTHR>>>(tokens, emb, k0, b0);
    rnn_kernel<<<NCTA, NTHR, SMEM_BYTES>>>(rk0, rk1, k1, b1, wd, bd, out);
}